// round 10
// baseline (speedup 1.0000x reference)
#include <cuda_runtime.h>
#include <math.h>

#define B 128

__device__ float g_h1[B * 1024];
__device__ float g_h2[B * 512];
__device__ float g_h3[B * 256];

__device__ __forceinline__ float ex2f(float x) {
    float y;
    asm("ex2.approx.f32 %0, %1;" : "=f"(y) : "f"(x));
    return y;
}

// identity on [0,1], slope 0.1 outside
__device__ __forceinline__ float leaky_clamp01(float w) {
    float r = w;
    if (w < 0.0f)      r = 0.1f * w;
    else if (w > 1.0f) r = 1.0f + 0.1f * (w - 1.0f);
    return r;
}

__device__ __forceinline__ float tau_scale(const float* taup, float tau_floor) {
    float ta  = __ldg(taup);
    float tau = tau_floor + (ta >= 0.0f ? ta : 0.05f * ta);  // leaky_relu
    return tau * 1.4426950408889634f;                        // tau * log2(e)
}

// ============================================================================
// Chunked kernel (big layers), software-pipelined staging:
// prefetch chunk c+1 (LDG->regs) before computing chunk c from smem buffer p,
// then STS into buffer 1-p; ONE __syncthreads per chunk. Double-buffered smem.
// Thread owns 2 outputs (oh, oh+OT/2) for batch row b, K range s*KR..(s+1)*KR
// of each chunk; S-way (num,den) partials reduced via smem.
//   out[b,o] = 1 - (sum e^arg * arg)/(cs * sum e^arg), arg = cs*h[b,i]*aw[o,i]
// CAT: layer-0 mode, h is x[B][IN/2], staged as concat(x, 1-x).
// ============================================================================
template <int IN, int BT, int OT, int KC, int S, bool CAT>
__global__ __launch_bounds__(BT*(OT/2)*S) void layer_chunked(
    const float* __restrict__ h, const float* __restrict__ W,
    const float* __restrict__ taup, float tau_floor,
    float* __restrict__ out, int out_dim) {
    constexpr int G   = BT * (OT / 2);
    constexpr int T   = G * S;
    constexpr int OH  = OT / 2;
    constexpr int KR  = KC / S;
    constexpr int KCP = KC + 4;
    constexpr int NC  = IN / KC;                // chunks
    constexpr int CHF = BT * (KC / 4) / T;      // ch float4 per thread
    constexpr int AWF = OT * (KC / 4) / T;      // aw float4 per thread
    static_assert(CHF * T == BT * (KC / 4), "ch staging must divide evenly");
    static_assert(AWF * T == OT * (KC / 4), "aw staging must divide evenly");

    __shared__ float  ch[2][BT * KCP];
    __shared__ float  aw[2][OT * KCP];
    __shared__ float4 rpart[S > 1 ? T : 1];

    const int tid   = threadIdx.x;
    const int obase = blockIdx.x * OT;
    const int bbase = blockIdx.y * BT;
    const int idx   = tid % G;
    const int s     = tid / G;
    const int b     = idx % BT;
    const int oh    = idx / BT;

    const float cs = tau_scale(taup, tau_floor);

    float4 vch[CHF], vaw[AWF];

    auto fetch = [&](int k0) {
        const int hk0  = CAT ? (k0 & (IN / 2 - 1)) : k0;
        const int hstr = CAT ? (IN / 2) : IN;
        #pragma unroll
        for (int j = 0; j < CHF; j++) {
            int i = tid + j * T;
            int bb = i / (KC / 4), kv = i - bb * (KC / 4);
            vch[j] = *(const float4*)&h[(bbase + bb) * hstr + hk0 + kv * 4];
        }
        #pragma unroll
        for (int j = 0; j < AWF; j++) {
            int i = tid + j * T;
            int oo = i / (KC / 4), kv = i - oo * (KC / 4);
            vaw[j] = *(const float4*)&W[(obase + oo) * IN + k0 + kv * 4];
        }
    };

    auto store = [&](int k0, int buf) {
        const bool inv  = CAT && (k0 >= IN / 2);
        const float sc  = inv ? -cs : cs;
        const float off = inv ?  cs : 0.0f;
        #pragma unroll
        for (int j = 0; j < CHF; j++) {
            int i = tid + j * T;
            int bb = i / (KC / 4), kv = i - bb * (KC / 4);
            float4 v = vch[j], r;
            r.x = fmaf(v.x, sc, off); r.y = fmaf(v.y, sc, off);
            r.z = fmaf(v.z, sc, off); r.w = fmaf(v.w, sc, off);
            *(float4*)&ch[buf][bb * KCP + kv * 4] = r;
        }
        #pragma unroll
        for (int j = 0; j < AWF; j++) {
            int i = tid + j * T;
            int oo = i / (KC / 4), kv = i - oo * (KC / 4);
            float4 v = vaw[j], r;
            r.x = leaky_clamp01(v.x); r.y = leaky_clamp01(v.y);
            r.z = leaky_clamp01(v.z); r.w = leaky_clamp01(v.w);
            *(float4*)&aw[buf][oo * KCP + kv * 4] = r;
        }
    };

    float num0 = 0.f, den0 = 0.f, num1 = 0.f, den1 = 0.f;

    // prologue: stage chunk 0
    fetch(0);
    store(0, 0);
    __syncthreads();

    int p = 0;
    #pragma unroll
    for (int c = 0; c < NC; c++) {
        if (c + 1 < NC) fetch((c + 1) * KC);   // LDGs in flight during compute

        const float* cp  = &ch[p][b * KCP + s * KR];
        const float* ap0 = &aw[p][oh * KCP + s * KR];
        const float* ap1 = &aw[p][(oh + OH) * KCP + s * KR];
        #pragma unroll 4
        for (int k = 0; k < KR; k += 4) {
            float4 cv = *(const float4*)&cp[k];
            float4 a0 = *(const float4*)&ap0[k];
            float4 a1 = *(const float4*)&ap1[k];
            float z;
            z = cv.x * a0.x; { float e = ex2f(z); den0 += e; num0 = fmaf(e, z, num0); }
            z = cv.y * a0.y; { float e = ex2f(z); den0 += e; num0 = fmaf(e, z, num0); }
            z = cv.z * a0.z; { float e = ex2f(z); den0 += e; num0 = fmaf(e, z, num0); }
            z = cv.w * a0.w; { float e = ex2f(z); den0 += e; num0 = fmaf(e, z, num0); }
            z = cv.x * a1.x; { float e = ex2f(z); den1 += e; num1 = fmaf(e, z, num1); }
            z = cv.y * a1.y; { float e = ex2f(z); den1 += e; num1 = fmaf(e, z, num1); }
            z = cv.z * a1.z; { float e = ex2f(z); den1 += e; num1 = fmaf(e, z, num1); }
            z = cv.w * a1.w; { float e = ex2f(z); den1 += e; num1 = fmaf(e, z, num1); }
        }

        if (c + 1 < NC) {
            store((c + 1) * KC, p ^ 1);
            __syncthreads();
            p ^= 1;
        }
    }

    if (S > 1) {
        rpart[tid] = make_float4(num0, den0, num1, den1);
        __syncthreads();
        if (s == 0) {
            #pragma unroll
            for (int ss = 1; ss < S; ss++) {
                float4 q = rpart[idx + ss * G];
                num0 += q.x; den0 += q.y; num1 += q.z; den1 += q.w;
            }
            const int bo = (bbase + b) * out_dim + obase + oh;
            out[bo]      = 1.0f - (num0 / den0) / cs;
            out[bo + OH] = 1.0f - (num1 / den1) / cs;
        }
    } else {
        const int bo = (bbase + b) * out_dim + obase + oh;
        out[bo]      = 1.0f - (num0 / den0) / cs;
        out[bo + OH] = 1.0f - (num1 / den1) / cs;
    }
}

// ============================================================================
// Split kernel (small layers, R5-proven). Whole input staged once; S threads
// per output, each covering IN/S of K; partials reduced via smem.
// ============================================================================
template <int IN, int BT, int OT, int S>
__global__ __launch_bounds__(BT * OT * S) void layer_split(
    const float* __restrict__ h, const float* __restrict__ W,
    const float* __restrict__ taup, float tau_floor,
    float* __restrict__ out, int out_dim) {
    constexpr int T   = BT * OT * S;
    constexpr int G   = BT * OT;
    constexpr int KR  = IN / S;
    constexpr int INP = IN + 4;
    __shared__ float ch[BT * INP];
    __shared__ float aw[OT * INP];
    __shared__ float2 rpart[T];

    const int tid   = threadIdx.x;
    const int obase = blockIdx.x * OT;
    const int bbase = blockIdx.y * BT;
    const int idx   = tid & (G - 1);
    const int s     = tid / G;
    const int b     = idx % BT;
    const int o     = idx / BT;

    const float cs = tau_scale(taup, tau_floor);

    #pragma unroll
    for (int i = tid; i < BT * (IN / 4); i += T) {
        int bb = i / (IN / 4), kv = i - bb * (IN / 4);
        float4 v = *(const float4*)&h[(bbase + bb) * IN + kv * 4];
        float4 r; r.x = v.x * cs; r.y = v.y * cs; r.z = v.z * cs; r.w = v.w * cs;
        *(float4*)&ch[bb * INP + kv * 4] = r;
    }
    #pragma unroll
    for (int i = tid; i < OT * (IN / 4); i += T) {
        int oo = i / (IN / 4), kv = i - oo * (IN / 4);
        float4 v = *(const float4*)&W[(obase + oo) * IN + kv * 4];
        float4 r;
        r.x = leaky_clamp01(v.x); r.y = leaky_clamp01(v.y);
        r.z = leaky_clamp01(v.z); r.w = leaky_clamp01(v.w);
        *(float4*)&aw[oo * INP + kv * 4] = r;
    }
    __syncthreads();

    float num = 0.0f, den = 0.0f;
    const float* cp = &ch[b * INP + s * KR];
    const float* ap = &aw[o * INP + s * KR];
    #pragma unroll 4
    for (int k = 0; k < KR; k += 4) {
        float4 c = *(const float4*)&cp[k];
        float4 a = *(const float4*)&ap[k];
        float z;
        z = c.x * a.x; { float e = ex2f(z); den += e; num = fmaf(e, z, num); }
        z = c.y * a.y; { float e = ex2f(z); den += e; num = fmaf(e, z, num); }
        z = c.z * a.z; { float e = ex2f(z); den += e; num = fmaf(e, z, num); }
        z = c.w * a.w; { float e = ex2f(z); den += e; num = fmaf(e, z, num); }
    }

    rpart[tid] = make_float2(num, den);
    __syncthreads();
    if (s == 0) {
        #pragma unroll
        for (int ss = 1; ss < S; ss++) {
            float2 p = rpart[idx + ss * G];
            num += p.x;
            den += p.y;
        }
        out[(bbase + b) * out_dim + obase + o] = 1.0f - (num / den) / cs;
    }
}

extern "C" void kernel_launch(void* const* d_in, const int* in_sizes, int n_in,
                              void* d_out, int out_size) {
    // metadata order: x, W0, tau0, W1, tau1, W2, tau2, W3, tau3
    const float* x  = (const float*)d_in[0];
    const float* W0 = (const float*)d_in[1];
    const float* t0 = (const float*)d_in[2];
    const float* W1 = (const float*)d_in[3];
    const float* t1 = (const float*)d_in[4];
    const float* W2 = (const float*)d_in[5];
    const float* t2 = (const float*)d_in[6];
    const float* W3 = (const float*)d_in[7];
    const float* t3 = (const float*)d_in[8];
    float* out = (float*)d_out;

    float *h1, *h2, *h3;
    cudaGetSymbolAddress((void**)&h1, g_h1);
    cudaGetSymbolAddress((void**)&h2, g_h2);
    cudaGetSymbolAddress((void**)&h3, g_h3);

    // tau_floor = log(in-1) + log(0.95/0.05)
    const float L19 = 2.9444389791664403f;
    const float tf0 = logf(1023.0f) + L19;
    const float tf1 = logf(1023.0f) + L19;
    const float tf2 = logf(511.0f)  + L19;
    const float tf3 = logf(255.0f)  + L19;

    // L0: 1024->1024, fused concat, pipelined, S=2. 512 blocks x 256 thr.
    layer_chunked<1024, 8, 32, 256, 2, true>
        <<<dim3(1024 / 32, B / 8), 256>>>(x, W0, t0, tf0, h1, 1024);
    // L1: 1024->512, pipelined, S=2. 256 blocks x 256 thr.
    layer_chunked<1024, 8, 32, 256, 2, false>
        <<<dim3(512 / 32, B / 8), 256>>>(h1, W1, t1, tf1, h2, 512);
    // L2: 512->256, 4-way split. 512 blocks x 256 thr.
    layer_split<512, 8, 8, 4>
        <<<dim3(256 / 8, B / 8), 256>>>(h2, W2, t2, tf2, h3, 256);
    // L3: 256->128, 4-way split. 256 blocks x 256 thr.
    layer_split<256, 8, 8, 4>
        <<<dim3(128 / 8, B / 8), 256>>>(h3, W3, t3, tf3, out, 128);
}

// round 11
// speedup vs baseline: 1.4972x; 1.4972x over previous
#include <cuda_runtime.h>
#include <math.h>

#define B 128

__device__ float g_h1[B * 1024];
__device__ float g_h2[B * 512];
__device__ float g_h3[B * 256];

__device__ __forceinline__ float ex2f(float x) {
    float y;
    asm("ex2.approx.f32 %0, %1;" : "=f"(y) : "f"(x));
    return y;
}

// identity on [0,1], slope 0.1 outside
__device__ __forceinline__ float leaky_clamp01(float w) {
    float r = w;
    if (w < 0.0f)      r = 0.1f * w;
    else if (w > 1.0f) r = 1.0f + 0.1f * (w - 1.0f);
    return r;
}

__device__ __forceinline__ float tau_scale(const float* taup, float tau_floor) {
    float ta  = __ldg(taup);
    float tau = tau_floor + (ta >= 0.0f ? ta : 0.05f * ta);  // leaky_relu
    return tau * 1.4426950408889634f;                        // tau * log2(e)
}

// ============================================================================
// Chunked kernel (big layers) — R5-proven config. Thread owns 2 outputs
// (oh, oh+OT/2) for one batch row; float4 smem pipeline; rows padded by 4.
//   out[b,o] = 1 - (sum e^arg * arg)/(cs * sum e^arg), arg = cs*h[b,i]*aw[o,i]
// CAT: layer-0 mode, h is x[B][IN/2], staged as concat(x, 1-x).
// ============================================================================
template <int IN, int BT, int OT, int KC, bool CAT>
__global__ __launch_bounds__(BT * OT / 2, 4) void layer_chunked(
    const float* __restrict__ h, const float* __restrict__ W,
    const float* __restrict__ taup, float tau_floor,
    float* __restrict__ out, int out_dim) {
    constexpr int T   = BT * OT / 2;
    constexpr int OH  = OT / 2;
    constexpr int KCP = KC + 4;
    __shared__ float ch[BT * KCP];
    __shared__ float aw[OT * KCP];

    const int tid   = threadIdx.x;
    const int obase = blockIdx.x * OT;
    const int bbase = blockIdx.y * BT;
    const int b     = tid % BT;
    const int oh    = tid / BT;

    const float cs = tau_scale(taup, tau_floor);

    float num0 = 0.f, den0 = 0.f, num1 = 0.f, den1 = 0.f;

    for (int k0 = 0; k0 < IN; k0 += KC) {
        if (k0) __syncthreads();
        {   // stage activations (fused concat(x,1-x) for layer 0)
            const bool inv  = CAT && (k0 >= IN / 2);
            const float sc  = inv ? -cs : cs;
            const float off = inv ?  cs : 0.0f;
            const int hk0   = CAT ? (k0 & (IN / 2 - 1)) : k0;
            const int hstr  = CAT ? (IN / 2) : IN;
            #pragma unroll
            for (int i = tid; i < BT * (KC / 4); i += T) {
                int bb = i / (KC / 4), kv = i - bb * (KC / 4);
                float4 v = *(const float4*)&h[(bbase + bb) * hstr + hk0 + kv * 4];
                float4 r;
                r.x = fmaf(v.x, sc, off); r.y = fmaf(v.y, sc, off);
                r.z = fmaf(v.z, sc, off); r.w = fmaf(v.w, sc, off);
                *(float4*)&ch[bb * KCP + kv * 4] = r;
            }
        }
        #pragma unroll
        for (int i = tid; i < OT * (KC / 4); i += T) {
            int oo = i / (KC / 4), kv = i - oo * (KC / 4);
            float4 v = *(const float4*)&W[(obase + oo) * IN + k0 + kv * 4];
            float4 r;
            r.x = leaky_clamp01(v.x); r.y = leaky_clamp01(v.y);
            r.z = leaky_clamp01(v.z); r.w = leaky_clamp01(v.w);
            *(float4*)&aw[oo * KCP + kv * 4] = r;
        }
        __syncthreads();

        const float* cp  = &ch[b * KCP];
        const float* ap0 = &aw[oh * KCP];
        const float* ap1 = &aw[(oh + OH) * KCP];
        #pragma unroll 4
        for (int k = 0; k < KC; k += 4) {
            float4 c  = *(const float4*)&cp[k];
            float4 a0 = *(const float4*)&ap0[k];
            float4 a1 = *(const float4*)&ap1[k];
            float z;
            z = c.x * a0.x; { float e = ex2f(z); den0 += e; num0 = fmaf(e, z, num0); }
            z = c.y * a0.y; { float e = ex2f(z); den0 += e; num0 = fmaf(e, z, num0); }
            z = c.z * a0.z; { float e = ex2f(z); den0 += e; num0 = fmaf(e, z, num0); }
            z = c.w * a0.w; { float e = ex2f(z); den0 += e; num0 = fmaf(e, z, num0); }
            z = c.x * a1.x; { float e = ex2f(z); den1 += e; num1 = fmaf(e, z, num1); }
            z = c.y * a1.y; { float e = ex2f(z); den1 += e; num1 = fmaf(e, z, num1); }
            z = c.z * a1.z; { float e = ex2f(z); den1 += e; num1 = fmaf(e, z, num1); }
            z = c.w * a1.w; { float e = ex2f(z); den1 += e; num1 = fmaf(e, z, num1); }
        }
    }

    const int bo = (bbase + b) * out_dim + obase + oh;
    out[bo]      = 1.0f - (num0 / den0) / cs;
    out[bo + OH] = 1.0f - (num1 / den1) / cs;
}

// ============================================================================
// Warp-per-output kernel (small layers). One warp computes one (b, o):
// lanes split K 32 ways with coalesced LDG.128 directly from L2/L1 (no smem,
// no barriers); (num, den) combined via 5-level butterfly shuffle.
// Blocks of 8 warps share one W row (b varies fastest) -> W reads are L1-hot.
// ============================================================================
template <int IN>
__global__ __launch_bounds__(256) void layer_warp(
    const float* __restrict__ h, const float* __restrict__ W,
    const float* __restrict__ taup, float tau_floor,
    float* __restrict__ out, int out_dim) {
    const int gw = blockIdx.x * (blockDim.x >> 5) + (threadIdx.x >> 5);
    const int l  = threadIdx.x & 31;
    const int b  = gw & (B - 1);     // batch varies fastest within a block
    const int o  = gw >> 7;          // / B

    const float cs = tau_scale(taup, tau_floor);

    const float* hp = h + b * IN;
    const float* wp = W + o * IN;

    float num = 0.0f, den = 0.0f;
    #pragma unroll
    for (int j = 0; j < IN / 128; j++) {
        float4 hv = *(const float4*)&hp[j * 128 + l * 4];
        float4 wv = *(const float4*)&wp[j * 128 + l * 4];
        float z;
        z = (cs * hv.x) * leaky_clamp01(wv.x); { float e = ex2f(z); den += e; num = fmaf(e, z, num); }
        z = (cs * hv.y) * leaky_clamp01(wv.y); { float e = ex2f(z); den += e; num = fmaf(e, z, num); }
        z = (cs * hv.z) * leaky_clamp01(wv.z); { float e = ex2f(z); den += e; num = fmaf(e, z, num); }
        z = (cs * hv.w) * leaky_clamp01(wv.w); { float e = ex2f(z); den += e; num = fmaf(e, z, num); }
    }

    #pragma unroll
    for (int off = 16; off > 0; off >>= 1) {
        num += __shfl_xor_sync(0xFFFFFFFFu, num, off);
        den += __shfl_xor_sync(0xFFFFFFFFu, den, off);
    }

    if (l == 0)
        out[b * out_dim + o] = 1.0f - (num / den) / cs;
}

extern "C" void kernel_launch(void* const* d_in, const int* in_sizes, int n_in,
                              void* d_out, int out_size) {
    // metadata order: x, W0, tau0, W1, tau1, W2, tau2, W3, tau3
    const float* x  = (const float*)d_in[0];
    const float* W0 = (const float*)d_in[1];
    const float* t0 = (const float*)d_in[2];
    const float* W1 = (const float*)d_in[3];
    const float* t1 = (const float*)d_in[4];
    const float* W2 = (const float*)d_in[5];
    const float* t2 = (const float*)d_in[6];
    const float* W3 = (const float*)d_in[7];
    const float* t3 = (const float*)d_in[8];
    float* out = (float*)d_out;

    float *h1, *h2, *h3;
    cudaGetSymbolAddress((void**)&h1, g_h1);
    cudaGetSymbolAddress((void**)&h2, g_h2);
    cudaGetSymbolAddress((void**)&h3, g_h3);

    // tau_floor = log(in-1) + log(0.95/0.05)
    const float L19 = 2.9444389791664403f;
    const float tf0 = logf(1023.0f) + L19;
    const float tf1 = logf(1023.0f) + L19;
    const float tf2 = logf(511.0f)  + L19;
    const float tf3 = logf(255.0f)  + L19;

    // L0: 1024->1024, fused concat. 512 blocks x 128 thr (R5-proven).
    layer_chunked<1024, 8, 32, 256, true>
        <<<dim3(1024 / 32, B / 8), 128>>>(x, W0, t0, tf0, h1, 1024);
    // L1: 1024->512. 256 blocks x 128 thr (R5-proven).
    layer_chunked<1024, 8, 32, 256, false>
        <<<dim3(512 / 32, B / 8), 128>>>(h1, W1, t1, tf1, h2, 512);
    // L2: 512->256. Warp-per-output: 128*256 = 32768 warps, 4096 blocks.
    layer_warp<512><<<(B * 256) / 8, 256>>>(h2, W2, t2, tf2, h3, 256);
    // L3: 256->128. Warp-per-output: 128*128 = 16384 warps, 2048 blocks.
    layer_warp<256><<<(B * 128) / 8, 256>>>(h3, W3, t3, tf3, out, 128);
}

// round 12
// speedup vs baseline: 1.6466x; 1.0998x over previous
#include <cuda_runtime.h>
#include <math.h>

#define B 128

__device__ float g_h1[B * 1024];
__device__ float g_h2[B * 512];
__device__ float g_h3[B * 256];

__device__ __forceinline__ float ex2f(float x) {
    float y;
    asm("ex2.approx.f32 %0, %1;" : "=f"(y) : "f"(x));
    return y;
}

// identity on [0,1], slope 0.1 outside
__device__ __forceinline__ float leaky_clamp01(float w) {
    float r = w;
    if (w < 0.0f)      r = 0.1f * w;
    else if (w > 1.0f) r = 1.0f + 0.1f * (w - 1.0f);
    return r;
}

__device__ __forceinline__ float tau_scale(const float* taup, float tau_floor) {
    float ta  = __ldg(taup);
    float tau = tau_floor + (ta >= 0.0f ? ta : 0.05f * ta);  // leaky_relu
    return tau * 1.4426950408889634f;                        // tau * log2(e)
}

// ============================================================================
// Chunked kernel (big layers), OPT=1: thread owns ONE (b,o) output.
// 128-thread blocks (4 warps = exactly 1 per SMSP), many blocks -> even
// per-SM MUFU load. Rows padded by 4 floats for float4 LDS without conflicts.
//   out[b,o] = 1 - (sum e^arg * arg)/(cs * sum e^arg), arg = cs*h[b,i]*aw[o,i]
// CAT: layer-0 mode, h is x[B][IN/2], staged as concat(x, 1-x).
// ============================================================================
template <int IN, int BT, int OT, int KC, bool CAT>
__global__ __launch_bounds__(BT * OT) void layer_chunked(
    const float* __restrict__ h, const float* __restrict__ W,
    const float* __restrict__ taup, float tau_floor,
    float* __restrict__ out, int out_dim) {
    constexpr int T   = BT * OT;
    constexpr int KCP = KC + 4;
    __shared__ float ch[BT * KCP];
    __shared__ float aw[OT * KCP];

    const int tid   = threadIdx.x;
    const int obase = blockIdx.x * OT;
    const int bbase = blockIdx.y * BT;
    const int b     = tid % BT;
    const int o     = tid / BT;

    const float cs = tau_scale(taup, tau_floor);

    float num = 0.f, den = 0.f;

    for (int k0 = 0; k0 < IN; k0 += KC) {
        if (k0) __syncthreads();
        {   // stage activations (fused concat(x,1-x) for layer 0)
            const bool inv  = CAT && (k0 >= IN / 2);
            const float sc  = inv ? -cs : cs;
            const float off = inv ?  cs : 0.0f;
            const int hk0   = CAT ? (k0 & (IN / 2 - 1)) : k0;
            const int hstr  = CAT ? (IN / 2) : IN;
            #pragma unroll
            for (int i = tid; i < BT * (KC / 4); i += T) {
                int bb = i / (KC / 4), kv = i - bb * (KC / 4);
                float4 v = *(const float4*)&h[(bbase + bb) * hstr + hk0 + kv * 4];
                float4 r;
                r.x = fmaf(v.x, sc, off); r.y = fmaf(v.y, sc, off);
                r.z = fmaf(v.z, sc, off); r.w = fmaf(v.w, sc, off);
                *(float4*)&ch[bb * KCP + kv * 4] = r;
            }
        }
        #pragma unroll
        for (int i = tid; i < OT * (KC / 4); i += T) {
            int oo = i / (KC / 4), kv = i - oo * (KC / 4);
            float4 v = *(const float4*)&W[(obase + oo) * IN + k0 + kv * 4];
            float4 r;
            r.x = leaky_clamp01(v.x); r.y = leaky_clamp01(v.y);
            r.z = leaky_clamp01(v.z); r.w = leaky_clamp01(v.w);
            *(float4*)&aw[oo * KCP + kv * 4] = r;
        }
        __syncthreads();

        const float* cp = &ch[b * KCP];
        const float* ap = &aw[o * KCP];
        #pragma unroll 8
        for (int k = 0; k < KC; k += 4) {
            float4 c = *(const float4*)&cp[k];
            float4 a = *(const float4*)&ap[k];
            float z;
            z = c.x * a.x; { float e = ex2f(z); den += e; num = fmaf(e, z, num); }
            z = c.y * a.y; { float e = ex2f(z); den += e; num = fmaf(e, z, num); }
            z = c.z * a.z; { float e = ex2f(z); den += e; num = fmaf(e, z, num); }
            z = c.w * a.w; { float e = ex2f(z); den += e; num = fmaf(e, z, num); }
        }
    }

    out[(bbase + b) * out_dim + obase + o] = 1.0f - (num / den) / cs;
}

// ============================================================================
// Split kernel (small layers, R5-proven shapes). Whole input staged once;
// S threads per output, each covering IN/S of K; partials reduced via smem.
// ============================================================================
template <int IN, int BT, int OT, int S>
__global__ __launch_bounds__(BT * OT * S) void layer_split(
    const float* __restrict__ h, const float* __restrict__ W,
    const float* __restrict__ taup, float tau_floor,
    float* __restrict__ out, int out_dim) {
    constexpr int T   = BT * OT * S;
    constexpr int G   = BT * OT;
    constexpr int KR  = IN / S;
    constexpr int INP = IN + 4;
    __shared__ float ch[BT * INP];
    __shared__ float aw[OT * INP];
    __shared__ float2 rpart[T];

    const int tid   = threadIdx.x;
    const int obase = blockIdx.x * OT;
    const int bbase = blockIdx.y * BT;
    const int idx   = tid & (G - 1);
    const int s     = tid / G;
    const int b     = idx % BT;
    const int o     = idx / BT;

    const float cs = tau_scale(taup, tau_floor);

    #pragma unroll
    for (int i = tid; i < BT * (IN / 4); i += T) {
        int bb = i / (IN / 4), kv = i - bb * (IN / 4);
        float4 v = *(const float4*)&h[(bbase + bb) * IN + kv * 4];
        float4 r; r.x = v.x * cs; r.y = v.y * cs; r.z = v.z * cs; r.w = v.w * cs;
        *(float4*)&ch[bb * INP + kv * 4] = r;
    }
    #pragma unroll
    for (int i = tid; i < OT * (IN / 4); i += T) {
        int oo = i / (IN / 4), kv = i - oo * (IN / 4);
        float4 v = *(const float4*)&W[(obase + oo) * IN + kv * 4];
        float4 r;
        r.x = leaky_clamp01(v.x); r.y = leaky_clamp01(v.y);
        r.z = leaky_clamp01(v.z); r.w = leaky_clamp01(v.w);
        *(float4*)&aw[oo * INP + kv * 4] = r;
    }
    __syncthreads();

    float num = 0.0f, den = 0.0f;
    const float* cp = &ch[b * INP + s * KR];
    const float* ap = &aw[o * INP + s * KR];
    #pragma unroll 4
    for (int k = 0; k < KR; k += 4) {
        float4 c = *(const float4*)&cp[k];
        float4 a = *(const float4*)&ap[k];
        float z;
        z = c.x * a.x; { float e = ex2f(z); den += e; num = fmaf(e, z, num); }
        z = c.y * a.y; { float e = ex2f(z); den += e; num = fmaf(e, z, num); }
        z = c.z * a.z; { float e = ex2f(z); den += e; num = fmaf(e, z, num); }
        z = c.w * a.w; { float e = ex2f(z); den += e; num = fmaf(e, z, num); }
    }

    rpart[tid] = make_float2(num, den);
    __syncthreads();
    if (s == 0) {
        #pragma unroll
        for (int ss = 1; ss < S; ss++) {
            float2 p = rpart[idx + ss * G];
            num += p.x;
            den += p.y;
        }
        out[(bbase + b) * out_dim + obase + o] = 1.0f - (num / den) / cs;
    }
}

extern "C" void kernel_launch(void* const* d_in, const int* in_sizes, int n_in,
                              void* d_out, int out_size) {
    // metadata order: x, W0, tau0, W1, tau1, W2, tau2, W3, tau3
    const float* x  = (const float*)d_in[0];
    const float* W0 = (const float*)d_in[1];
    const float* t0 = (const float*)d_in[2];
    const float* W1 = (const float*)d_in[3];
    const float* t1 = (const float*)d_in[4];
    const float* W2 = (const float*)d_in[5];
    const float* t2 = (const float*)d_in[6];
    const float* W3 = (const float*)d_in[7];
    const float* t3 = (const float*)d_in[8];
    float* out = (float*)d_out;

    float *h1, *h2, *h3;
    cudaGetSymbolAddress((void**)&h1, g_h1);
    cudaGetSymbolAddress((void**)&h2, g_h2);
    cudaGetSymbolAddress((void**)&h3, g_h3);

    // tau_floor = log(in-1) + log(0.95/0.05)
    const float L19 = 2.9444389791664403f;
    const float tf0 = logf(1023.0f) + L19;
    const float tf1 = logf(1023.0f) + L19;
    const float tf2 = logf(511.0f)  + L19;
    const float tf3 = logf(255.0f)  + L19;

    // L0: 1024->1024, fused concat. 1024 blocks x 128 thr (6.9 blk/SM, even).
    layer_chunked<1024, 8, 16, 256, true>
        <<<dim3(1024 / 16, B / 8), 128>>>(x, W0, t0, tf0, h1, 1024);
    // L1: 1024->512. 512 blocks x 128 thr.
    layer_chunked<1024, 8, 16, 256, false>
        <<<dim3(512 / 16, B / 8), 128>>>(h1, W1, t1, tf1, h2, 512);
    // L2: 512->256, 4-way split. 512 blocks x 256 thr (R5-proven).
    layer_split<512, 8, 8, 4>
        <<<dim3(256 / 8, B / 8), 256>>>(h2, W2, t2, tf2, h3, 256);
    // L3: 256->128, 4-way split. 256 blocks x 256 thr (R5-proven).
    layer_split<256, 8, 8, 4>
        <<<dim3(128 / 8, B / 8), 256>>>(h3, W3, t3, tf3, out, 128);
}